// round 1
// baseline (speedup 1.0000x reference)
#include <cuda_runtime.h>

// ----------------------------------------------------------------------------
// RadianceRenderer: 8192 rays x 64 samples, tiny NeRF MLP, fp32 + f32x2 FFMA2.
// Block = 1 ray (64 points), 128 threads, 2 blocks/SM.
// ----------------------------------------------------------------------------

#define T_SAMPLES 64
#define HID 128
#define STR 68                 // padded row stride for transposed activation tiles
#define SMEM_FLOATS 28560      // 114240 bytes -> 14 x 8KB pages -> 2 blocks/SM

typedef unsigned long long ull;

__device__ __forceinline__ ull pack2(float lo, float hi) {
    ull r;
    asm("mov.b64 %0, {%1, %2};" : "=l"(r)
        : "r"(__float_as_uint(lo)), "r"(__float_as_uint(hi)));
    return r;
}
__device__ __forceinline__ void unpack2(ull v, float& lo, float& hi) {
    unsigned a, b;
    asm("mov.b64 {%0, %1}, %2;" : "=r"(a), "=r"(b) : "l"(v));
    lo = __uint_as_float(a);
    hi = __uint_as_float(b);
}
__device__ __forceinline__ void fma2(ull& d, ull a, ull b) {
    asm("fma.rn.f32x2 %0, %1, %2, %0;" : "+l"(d) : "l"(a), "l"(b));
}

// GEMM tile: 64 points x 128 cols, K inner dim.
// Thread (tx = tid&31, ty = tid>>5) owns cols [tx*4, tx*4+4) x points [ty*16, ty*16+16).
// w: row-major [K][128] in smem.  a: transposed activations [K][STR] in smem.
template <int K>
__device__ __forceinline__ void gemm_tile(const float* __restrict__ w,
                                          const float* __restrict__ a,
                                          int cb, int pb, ull acc[4][8]) {
#pragma unroll 4
    for (int k = 0; k < K; k++) {
        float4 w4 = *(const float4*)(w + k * HID + cb);
        ull wp0 = pack2(w4.x, w4.x);
        ull wp1 = pack2(w4.y, w4.y);
        ull wp2 = pack2(w4.z, w4.z);
        ull wp3 = pack2(w4.w, w4.w);
        const ulonglong2* hp = (const ulonglong2*)(a + k * STR + pb);
        ulonglong2 u0 = hp[0], u1 = hp[1], u2 = hp[2], u3 = hp[3];
        ull hh[8] = {u0.x, u0.y, u1.x, u1.y, u2.x, u2.y, u3.x, u3.y};
#pragma unroll
        for (int i = 0; i < 8; i++) {
            fma2(acc[0][i], wp0, hh[i]);
            fma2(acc[1][i], wp1, hh[i]);
            fma2(acc[2][i], wp2, hh[i]);
            fma2(acc[3][i], wp3, hh[i]);
        }
    }
}

// Write tile back transposed (dst[col][p]) with bias + relu. Conflict-free STS.128.
__device__ __forceinline__ void write_tile(float* __restrict__ dst,
                                           const float* __restrict__ bias,
                                           int cb, int pb, ull acc[4][8]) {
#pragma unroll
    for (int c = 0; c < 4; c++) {
        float bb = bias[cb + c];
        float v[16];
#pragma unroll
        for (int i = 0; i < 8; i++) {
            float lo, hi;
            unpack2(acc[c][i], lo, hi);
            v[2 * i]     = fmaxf(lo + bb, 0.f);
            v[2 * i + 1] = fmaxf(hi + bb, 0.f);
        }
        float4* d = (float4*)(dst + (cb + c) * STR + pb);
        d[0] = make_float4(v[0], v[1], v[2], v[3]);
        d[1] = make_float4(v[4], v[5], v[6], v[7]);
        d[2] = make_float4(v[8], v[9], v[10], v[11]);
        d[3] = make_float4(v[12], v[13], v[14], v[15]);
    }
}

__global__ __launch_bounds__(128, 2) void radiance_kernel(
    const float* __restrict__ rays_o, const float* __restrict__ rays_d,
    const float* __restrict__ aabb,
    const float* __restrict__ W1, const float* __restrict__ b1,
    const float* __restrict__ W2, const float* __restrict__ b2,
    const float* __restrict__ Wd, const float* __restrict__ bd,
    const float* __restrict__ Wf, const float* __restrict__ bf,
    const float* __restrict__ Wc1, const float* __restrict__ bc1,
    const float* __restrict__ Wc2, const float* __restrict__ bc2,
    float* __restrict__ out) {
    extern __shared__ float sm[];
    float* sw2   = sm;            // 16384 (W2; later: Wall@0, Wc1@2560, Wc2@6912)
    float* bufA  = sm + 16384;    // 8704  (h1T -> h2T -> hcT, [128][STR])
    float* in32  = sm + 25088;    // 2176  ([32][STR]: feat rows 0..15, ynm 16..31)
    float* w1b   = sm + 27264;    // 512   (W1 3x128 + b1)
    float* sxyz  = sm + 27776;    // 192
    float* sts   = sm + 27968;    // 64
    float* ssig  = sm + 28032;    // 64
    float* scol  = sm + 28096;    // 320   (color, reused as reduction buffer)
    float* sscan = sm + 28416;    // 64
    float* synm  = sm + 28480;    // 16
    float* sins  = sm + 28496;    // 64

    const int tid = threadIdx.x;
    const int ray = blockIdx.x;
    const int tx = tid & 31, ty = tid >> 5;
    const int cb = tx * 4, pb = ty * 16;

    // ---- stage W2 into shared (coalesced float4) ----
    {
        const float4* g = (const float4*)W2;
        float4* s = (float4*)sw2;
#pragma unroll
        for (int i = 0; i < 32; i++) s[tid + i * 128] = g[tid + i * 128];
    }
    // W1 + b1 into shared
    w1b[tid]       = W1[tid];
    w1b[128 + tid] = W1[128 + tid];
    w1b[256 + tid] = W1[256 + tid];
    w1b[384 + tid] = b1[tid];

    // ---- ray setup (all threads, redundant & deterministic) ----
    float ox = rays_o[ray * 3 + 0], oy = rays_o[ray * 3 + 1], oz = rays_o[ray * 3 + 2];
    float dx = rays_d[ray * 3 + 0], dy = rays_d[ray * 3 + 1], dz = rays_d[ray * 3 + 2];
    float a0x = aabb[0], a0y = aabb[1], a0z = aabb[2];
    float a1x = aabb[3], a1y = aabb[4], a1z = aabb[5];
    float ix = 1.f / dx, iy = 1.f / dy, iz = 1.f / dz;
    float t1x = (a0x - ox) * ix, t2x = (a1x - ox) * ix;
    float t1y = (a0y - oy) * iy, t2y = (a1y - oy) * iy;
    float t1z = (a0z - oz) * iz, t2z = (a1z - oz) * iz;
    float tn = fmaxf(fmaxf(fminf(t1x, t2x), fminf(t1y, t2y)), fminf(t1z, t2z));
    tn = fmaxf(tn, 0.f);
    float tf = fminf(fminf(fmaxf(t1x, t2x), fmaxf(t1y, t2y)), fmaxf(t1z, t2z));
    tf = fminf(tf, 10.f);
    bool active = tn < tf;
    if (!active) { tn = 0.f; tf = 1.f; }
    float dnorm = sqrtf(dx * dx + dy * dy + dz * dz);

    if (tid == 0) {
        float inv = 1.f / dnorm;
        float x = dx * inv, y = dy * inv, z = dz * inv;
        float x2 = x * x, y2 = y * y, z2 = z * z;
        synm[0]  = 0.282094791773878f;
        synm[1]  = -0.488602511902920f * y;
        synm[2]  = 0.488602511902920f * z;
        synm[3]  = -0.488602511902920f * x;
        synm[4]  = 1.092548430592079f * x * y;
        synm[5]  = -1.092548430592079f * y * z;
        synm[6]  = 0.315391565252520f * (3.0f * z2 - 1.0f);
        synm[7]  = -1.092548430592079f * x * z;
        synm[8]  = 0.546274215296040f * (x2 - y2);
        synm[9]  = -0.590043589926644f * y * (3.0f * x2 - y2);
        synm[10] = 2.890611442640554f * x * y * z;
        synm[11] = -0.457045799464466f * y * (5.0f * z2 - 1.0f);
        synm[12] = 0.373176332590115f * z * (5.0f * z2 - 3.0f);
        synm[13] = -0.457045799464466f * x * (5.0f * z2 - 1.0f);
        synm[14] = 1.445305721320277f * z * (x2 - y2);
        synm[15] = -0.590043589926644f * x * (x2 - 3.0f * y2);
    }

    if (tid < 64) {
        float fr = (tid + 0.5f) * (1.f / 64.f);
        float t = tn + fr * (tf - tn);
        sts[tid] = t;
        float px = fmaf(dx, t, ox), py = fmaf(dy, t, oy), pz = fmaf(dz, t, oz);
        float nx = (px - a0x) / (a1x - a0x) * 2.f - 1.f;
        float ny = (py - a0y) / (a1y - a0y) * 2.f - 1.f;
        float nz = (pz - a0z) / (a1z - a0z) * 2.f - 1.f;
        sxyz[tid * 3 + 0] = nx;
        sxyz[tid * 3 + 1] = ny;
        sxyz[tid * 3 + 2] = nz;
        bool inside = (nx >= -1.f) && (nx <= 1.f) && (ny >= -1.f) && (ny <= 1.f) &&
                      (nz >= -1.f) && (nz <= 1.f);
        sins[tid] = inside ? 1.f : 0.f;
    }
    __syncthreads();

    // ---- layer 1: h1T[j][p] = relu(xyz_ndc . W1[:,j] + b1[j]) ----
    {
        int p = tid & 63;
        int j0 = (tid >> 6) * 64;
        float nx = sxyz[p * 3], ny = sxyz[p * 3 + 1], nz = sxyz[p * 3 + 2];
#pragma unroll 4
        for (int j = j0; j < j0 + 64; j++) {
            float v = w1b[384 + j];
            v = fmaf(nx, w1b[j], v);
            v = fmaf(ny, w1b[128 + j], v);
            v = fmaf(nz, w1b[256 + j], v);
            bufA[j * STR + p] = fmaxf(v, 0.f);
        }
        // fill ynm rows of in32 (rows 16..31)
        for (int idx = tid; idx < 16 * 64; idx += 128) {
            int i = idx >> 6, pp = idx & 63;
            in32[(16 + i) * STR + pp] = synm[i];
        }
    }
    __syncthreads();

    // ---- layer 2: h2 = relu(h1 @ W2 + b2)  (the big GEMM, FFMA2) ----
    ull acc[4][8];
#pragma unroll
    for (int c = 0; c < 4; c++)
#pragma unroll
        for (int i = 0; i < 8; i++) acc[c][i] = 0ULL;
    gemm_tile<HID>(sw2, bufA, cb, pb, acc);
    __syncthreads();                 // all h1T/W2 reads done
    write_tile(bufA, b2, cb, pb, acc);  // h2T overwrites h1T

    // stage small weights into (now free) sw2 region:
    // Wall [128][17] (Wf | Wd) @0, Wc1 [32][128] @2560, Wc2 [128][3] @6912
    for (int idx = tid; idx < 128 * 17; idx += 128) {
        int k = idx / 17, o = idx - k * 17;
        sw2[idx] = (o < 16) ? Wf[k * 16 + o] : Wd[k];
    }
    for (int idx = tid; idx < 32 * 128; idx += 128) sw2[2560 + idx] = Wc1[idx];
    for (int idx = tid; idx < 128 * 3; idx += 128) sw2[6912 + idx] = Wc2[idx];
    __syncthreads();

    // ---- sigma + feat: [128]->17 per point ----
    {
        int p = tid & 63;
        if (tid < 64) {
            float a[9] = {0, 0, 0, 0, 0, 0, 0, 0, 0};
#pragma unroll 4
            for (int k = 0; k < HID; k++) {
                float hv = bufA[k * STR + p];
                const float* wr = sw2 + k * 17;
#pragma unroll
                for (int m = 0; m < 9; m++) a[m] = fmaf(hv, wr[m], a[m]);
            }
#pragma unroll
            for (int m = 0; m < 9; m++) in32[m * STR + p] = a[m] + bf[m];
        } else {
            float a[8] = {0, 0, 0, 0, 0, 0, 0, 0};
#pragma unroll 4
            for (int k = 0; k < HID; k++) {
                float hv = bufA[k * STR + p];
                const float* wr = sw2 + k * 17 + 9;
#pragma unroll
                for (int m = 0; m < 8; m++) a[m] = fmaf(hv, wr[m], a[m]);
            }
#pragma unroll
            for (int m = 0; m < 7; m++) in32[(9 + m) * STR + p] = a[m] + bf[9 + m];
            ssig[p] = expf(a[7] + bd[0]) * sins[p];  // sigma masked by inside
        }
    }
    __syncthreads();

    // ---- layer c1: hc = relu([feat, ynm] @ Wc1 + bc1), K=32 ----
    ull acc2[4][8];
#pragma unroll
    for (int c = 0; c < 4; c++)
#pragma unroll
        for (int i = 0; i < 8; i++) acc2[c][i] = 0ULL;
    gemm_tile<32>(sw2 + 2560, in32, cb, pb, acc2);
    __syncthreads();
    write_tile(bufA, bc1, cb, pb, acc2);  // hcT overwrites h2T
    __syncthreads();

    // ---- layer c2: color = sigmoid(hc @ Wc2 + bc2) * inside ----
    {
        int p = tid & 63;
        float m = sins[p];
        if (tid < 64) {
            float a0 = 0.f, a1 = 0.f;
#pragma unroll 4
            for (int k = 0; k < HID; k++) {
                float hv = bufA[k * STR + p];
                a0 = fmaf(hv, sw2[6912 + k * 3 + 0], a0);
                a1 = fmaf(hv, sw2[6912 + k * 3 + 1], a1);
            }
            scol[p * 5 + 0] = m / (1.f + expf(-(a0 + bc2[0])));
            scol[p * 5 + 1] = m / (1.f + expf(-(a1 + bc2[1])));
        } else {
            float a2 = 0.f;
#pragma unroll 4
            for (int k = 0; k < HID; k++) {
                float hv = bufA[k * STR + p];
                a2 = fmaf(hv, sw2[6912 + k * 3 + 2], a2);
            }
            scol[p * 5 + 2] = m / (1.f + expf(-(a2 + bc2[2])));
        }
    }
    __syncthreads();

    // ---- integration: tau, exclusive cumsum, weights, reductions ----
    float tau = 0.f;
    if (tid < 64) {
        float t = sts[tid];
        float tnext = (tid < 63) ? sts[tid + 1] : (tf + 1.0f);  // BOOSTER = 1.0
        tau = ssig[tid] * (tnext - t) * dnorm;
        sscan[tid] = tau;
    }
    __syncthreads();
    // inclusive Hillis-Steele scan over 64 elems
#pragma unroll
    for (int off = 1; off < 64; off <<= 1) {
        float v = 0.f;
        if (tid < 64 && tid >= off) v = sscan[tid - off];
        __syncthreads();
        if (tid < 64) sscan[tid] += v;
        __syncthreads();
    }
    if (tid < 64) {
        float excl = (tid > 0) ? sscan[tid - 1] : 0.f;
        float wgt = expf(-excl) * (1.f - expf(-tau));
        float c0 = scol[tid * 5 + 0];
        float c1 = scol[tid * 5 + 1];
        float c2 = scol[tid * 5 + 2];
        float t = sts[tid];
        scol[tid * 5 + 0] = wgt * c0;
        scol[tid * 5 + 1] = wgt * c1;
        scol[tid * 5 + 2] = wgt * c2;
        scol[tid * 5 + 3] = wgt;
        scol[tid * 5 + 4] = wgt * t;
    }
    __syncthreads();
#pragma unroll
    for (int off = 32; off >= 1; off >>= 1) {
        if (tid < off) {
#pragma unroll
            for (int q = 0; q < 5; q++) scol[tid * 5 + q] += scol[(tid + off) * 5 + q];
        }
        __syncthreads();
    }
    if (tid < 5) {
        float am = active ? 1.f : 0.f;
        out[ray * 5 + tid] = scol[tid] * am;
    }
}

extern "C" void kernel_launch(void* const* d_in, const int* in_sizes, int n_in,
                              void* d_out, int out_size) {
    const float* rays_o = (const float*)d_in[0];
    const float* rays_d = (const float*)d_in[1];
    const float* aabb   = (const float*)d_in[2];
    const float* W1  = (const float*)d_in[3];
    const float* b1  = (const float*)d_in[4];
    const float* W2  = (const float*)d_in[5];
    const float* b2  = (const float*)d_in[6];
    const float* Wd  = (const float*)d_in[7];
    const float* bd  = (const float*)d_in[8];
    const float* Wf  = (const float*)d_in[9];
    const float* bf  = (const float*)d_in[10];
    const float* Wc1 = (const float*)d_in[11];
    const float* bc1 = (const float*)d_in[12];
    const float* Wc2 = (const float*)d_in[13];
    const float* bc2 = (const float*)d_in[14];
    float* out = (float*)d_out;

    int n_rays = in_sizes[0] / 3;
    size_t smem = SMEM_FLOATS * sizeof(float);
    cudaFuncSetAttribute(radiance_kernel, cudaFuncAttributeMaxDynamicSharedMemorySize,
                         (int)smem);
    radiance_kernel<<<n_rays, 128, smem>>>(rays_o, rays_d, aabb, W1, b1, W2, b2, Wd, bd,
                                           Wf, bf, Wc1, bc1, Wc2, bc2, out);
}